// round 1
// baseline (speedup 1.0000x reference)
#include <cuda_runtime.h>
#include <math.h>

#define EPS 1e-6f
constexpr int B = 2, P = 2048, D = 768, H = 12, HD = 64;
constexpr int TOK = B * P;        // 4096
constexpr int QKVN = 3 * D;       // 2304

// ---------------- scratch (static device globals; no allocation) ----------------
__device__ float g_qkv[TOK * QKVN];       // qkv projection, token-major [tok][2304]
__device__ float g_qln[B * H * P * HD];   // layernormed q (* hd^-0.5), [bh][p][hd]
__device__ float g_kln[B * H * P * HD];   // layernormed k,               [bh][p][hd]
__device__ float g_att[TOK * D];          // attention output, token-major
__device__ float g_ln2[TOK * D];          // final LN output

// =========================================================================
// Tiled fp32 GEMM: C[M,N] = A[M,K] @ Bm[K,N] (+ bias).  128x128x16 tile,
// 256 threads, 8x8 microtile, float4 smem fragments.
// =========================================================================
__global__ __launch_bounds__(256) void gemm128(
    const float* __restrict__ A, const float* __restrict__ Bm,
    const float* __restrict__ bias, float* __restrict__ C,
    int M, int N, int K)
{
    __shared__ float As[16][132];   // [k][m], transposed for vector frag loads
    __shared__ float Bs[16][132];   // [k][n]

    int tid = threadIdx.x;
    int tx = tid & 15, ty = tid >> 4;
    int bn = blockIdx.x * 128, bm = blockIdx.y * 128;

    float acc[8][8];
#pragma unroll
    for (int i = 0; i < 8; i++)
#pragma unroll
        for (int j = 0; j < 8; j++) acc[i][j] = 0.f;

    for (int k0 = 0; k0 < K; k0 += 16) {
#pragma unroll
        for (int i = 0; i < 8; i++) {
            int l = tid + i * 256;                 // 0..2047
            As[l & 15][l >> 4] = A[(size_t)(bm + (l >> 4)) * K + k0 + (l & 15)];
        }
#pragma unroll
        for (int i = 0; i < 8; i++) {
            int l = tid + i * 256;
            Bs[l >> 7][l & 127] = Bm[(size_t)(k0 + (l >> 7)) * N + bn + (l & 127)];
        }
        __syncthreads();
#pragma unroll
        for (int k = 0; k < 16; k++) {
            float4 a0 = *(const float4*)&As[k][ty * 8];
            float4 a1 = *(const float4*)&As[k][ty * 8 + 4];
            float4 b0 = *(const float4*)&Bs[k][tx * 8];
            float4 b1 = *(const float4*)&Bs[k][tx * 8 + 4];
            float a[8] = {a0.x, a0.y, a0.z, a0.w, a1.x, a1.y, a1.z, a1.w};
            float b[8] = {b0.x, b0.y, b0.z, b0.w, b1.x, b1.y, b1.z, b1.w};
#pragma unroll
            for (int i = 0; i < 8; i++)
#pragma unroll
                for (int j = 0; j < 8; j++)
                    acc[i][j] = fmaf(a[i], b[j], acc[i][j]);
        }
        __syncthreads();
    }

#pragma unroll
    for (int i = 0; i < 8; i++) {
        int row = bm + ty * 8 + i;
#pragma unroll
        for (int j = 0; j < 8; j++) {
            int col = bn + tx * 8 + j;
            float v = acc[i][j];
            if (bias) v += bias[col];
            C[(size_t)row * N + col] = v;
        }
    }
}

// =========================================================================
// Per-head LayerNorm over hd=64 for q and k.  One warp per (kind, b, h, p).
// q additionally scaled by hd^-0.5 = 0.125.
// =========================================================================
__global__ __launch_bounds__(256) void ln_qk(
    const float* __restrict__ qs, const float* __restrict__ qb,
    const float* __restrict__ ks, const float* __restrict__ kb)
{
    int gw = (blockIdx.x * blockDim.x + threadIdx.x) >> 5;   // global warp id
    int lane = threadIdx.x & 31;
    const int ROWS = B * H * P;          // 49152 per kind
    int kind = gw / ROWS;                // 0 = q, 1 = k
    int idx = gw - kind * ROWS;
    int b = idx / (H * P);
    int h = (idx / P) % H;
    int p = idx % P;

    const float* src = g_qkv + (size_t)(b * P + p) * QKVN + kind * D + h * HD;
    float x0 = src[lane], x1 = src[lane + 32];

    float s = x0 + x1;
#pragma unroll
    for (int o = 16; o; o >>= 1) s += __shfl_xor_sync(0xffffffffu, s, o);
    float mean = s * (1.0f / 64.0f);
    float d0 = x0 - mean, d1 = x1 - mean;
    float v = d0 * d0 + d1 * d1;
#pragma unroll
    for (int o = 16; o; o >>= 1) v += __shfl_xor_sync(0xffffffffu, v, o);
    float inv = rsqrtf(v * (1.0f / 64.0f) + EPS);

    const float* sc = kind ? ks : qs;
    const float* bi = kind ? kb : qb;
    float mul = kind ? 1.0f : 0.125f;    // q gets hd^-0.5 folded in
    float y0 = (d0 * inv * sc[lane] + bi[lane]) * mul;
    float y1 = (d1 * inv * sc[lane + 32] + bi[lane + 32]) * mul;

    float* dst = (kind ? g_kln : g_qln) + (size_t)((b * H + h) * P + p) * HD;
    dst[lane] = y0;
    dst[lane + 32] = y1;
}

// =========================================================================
// Flash attention: grid (B*H, P/128), 256 threads.  Q-tile 128, K-tile 64.
// Thread (ty 0..15, tx 0..15): rows ty*8..+7, key/dim cols tx*4..+3.
// =========================================================================
constexpr int SMEM_ATTN = (64 * 132 + 64 * 68 + 64 * 68 + 128 * 68) * 4;  // 103424 B

__global__ __launch_bounds__(256) void attn_kernel()
{
    extern __shared__ float sm[];
    float* Qs = sm;               // [d=64][row=128+pad4]  (d-major)
    float* Ks = Qs + 64 * 132;    // [d=64][key=64+pad4]   (d-major)
    float* Vs = Ks + 64 * 68;     // [key=64][dim=64+pad4]
    float* Ps = Vs + 64 * 68;     // [row=128][key=64+pad4]

    int bh = blockIdx.x;          // b*H + h
    int q0 = blockIdx.y * 128;
    int tid = threadIdx.x, tx = tid & 15, ty = tid >> 4;
    int b = bh / H, h = bh - b * H;

    const float* Qg = g_qln + (size_t)bh * P * HD + (size_t)q0 * HD;
    const float* Kg = g_kln + (size_t)bh * P * HD;
    const float* Vg = g_qkv + (size_t)b * P * QKVN + 2 * D + h * HD;  // + p*QKVN + d

    // load Q tile transposed: Qs[d][row]
#pragma unroll
    for (int i = 0; i < 32; i++) {
        int l = tid + i * 256;               // l = row*64 + d
        Qs[(l & 63) * 132 + (l >> 6)] = Qg[l];
    }

    float m[8], lsum[8], O[8][4];
#pragma unroll
    for (int i = 0; i < 8; i++) {
        m[i] = -1e30f; lsum[i] = 0.f;
#pragma unroll
        for (int j = 0; j < 4; j++) O[i][j] = 0.f;
    }

    for (int kb = 0; kb < P; kb += 64) {
        __syncthreads();   // previous iter done with Ks/Vs/Ps (also fences Qs load)
#pragma unroll
        for (int i = 0; i < 16; i++) {
            int l = tid + i * 256;           // l = key*64 + d
            int key = l >> 6, d = l & 63;
            Ks[d * 68 + key] = Kg[(size_t)(kb + key) * HD + d];
            Vs[key * 68 + d] = Vg[(size_t)(kb + key) * QKVN + d];
        }
        __syncthreads();

        float S[8][4];
#pragma unroll
        for (int i = 0; i < 8; i++)
#pragma unroll
            for (int j = 0; j < 4; j++) S[i][j] = 0.f;

#pragma unroll 4
        for (int d = 0; d < 64; d++) {
            float4 a0 = *(const float4*)&Qs[d * 132 + ty * 8];
            float4 a1 = *(const float4*)&Qs[d * 132 + ty * 8 + 4];
            float4 bb = *(const float4*)&Ks[d * 68 + tx * 4];
            float a[8] = {a0.x, a0.y, a0.z, a0.w, a1.x, a1.y, a1.z, a1.w};
            float bv[4] = {bb.x, bb.y, bb.z, bb.w};
#pragma unroll
            for (int i = 0; i < 8; i++)
#pragma unroll
                for (int j = 0; j < 4; j++)
                    S[i][j] = fmaf(a[i], bv[j], S[i][j]);
        }

        // online softmax update (reduce across the 16 tx threads, width-16 shfl)
#pragma unroll
        for (int i = 0; i < 8; i++) {
            float mx = fmaxf(fmaxf(S[i][0], S[i][1]), fmaxf(S[i][2], S[i][3]));
#pragma unroll
            for (int o = 8; o; o >>= 1)
                mx = fmaxf(mx, __shfl_xor_sync(0xffffffffu, mx, o, 16));
            float mn = fmaxf(m[i], mx);
            float corr = __expf(m[i] - mn);
            float p0 = __expf(S[i][0] - mn);
            float p1 = __expf(S[i][1] - mn);
            float p2 = __expf(S[i][2] - mn);
            float p3 = __expf(S[i][3] - mn);
            float ls = p0 + p1 + p2 + p3;
#pragma unroll
            for (int o = 8; o; o >>= 1)
                ls += __shfl_xor_sync(0xffffffffu, ls, o, 16);
            lsum[i] = lsum[i] * corr + ls;
            m[i] = mn;
            O[i][0] *= corr; O[i][1] *= corr; O[i][2] *= corr; O[i][3] *= corr;
            float4 pv = make_float4(p0, p1, p2, p3);
            *(float4*)&Ps[(ty * 8 + i) * 68 + tx * 4] = pv;
        }
        __syncthreads();

        // O += P @ V
#pragma unroll 4
        for (int kk = 0; kk < 64; kk++) {
            float4 v4 = *(const float4*)&Vs[kk * 68 + tx * 4];
            float vv[4] = {v4.x, v4.y, v4.z, v4.w};
#pragma unroll
            for (int i = 0; i < 8; i++) {
                float a = Ps[(ty * 8 + i) * 68 + kk];
                O[i][0] = fmaf(a, vv[0], O[i][0]);
                O[i][1] = fmaf(a, vv[1], O[i][1]);
                O[i][2] = fmaf(a, vv[2], O[i][2]);
                O[i][3] = fmaf(a, vv[3], O[i][3]);
            }
        }
    }

#pragma unroll
    for (int i = 0; i < 8; i++) {
        float invl = 1.0f / lsum[i];
        int row = q0 + ty * 8 + i;
        float4 o4 = make_float4(O[i][0] * invl, O[i][1] * invl,
                                O[i][2] * invl, O[i][3] * invl);
        *(float4*)&g_att[(size_t)(b * P + row) * D + h * HD + tx * 4] = o4;
    }
}

// =========================================================================
// Final LayerNorm over D=768.  One 256-thread block per token.
// =========================================================================
__global__ __launch_bounds__(256) void ln_final(
    const float* __restrict__ sc, const float* __restrict__ bi)
{
    __shared__ float red[8];
    int t = blockIdx.x;
    int tid = threadIdx.x;
    const float* x = g_att + (size_t)t * D;

    float v0 = x[tid], v1 = x[tid + 256], v2 = x[tid + 512];
    float s = v0 + v1 + v2;
#pragma unroll
    for (int o = 16; o; o >>= 1) s += __shfl_xor_sync(0xffffffffu, s, o);
    if ((tid & 31) == 0) red[tid >> 5] = s;
    __syncthreads();
    float tot = 0.f;
#pragma unroll
    for (int w = 0; w < 8; w++) tot += red[w];
    float mean = tot * (1.0f / 768.0f);

    float d0 = v0 - mean, d1 = v1 - mean, d2 = v2 - mean;
    float vv = d0 * d0 + d1 * d1 + d2 * d2;
#pragma unroll
    for (int o = 16; o; o >>= 1) vv += __shfl_xor_sync(0xffffffffu, vv, o);
    __syncthreads();               // done reading red before reuse
    if ((tid & 31) == 0) red[tid >> 5] = vv;
    __syncthreads();
    float vt = 0.f;
#pragma unroll
    for (int w = 0; w < 8; w++) vt += red[w];
    float inv = rsqrtf(vt * (1.0f / 768.0f) + EPS);

    float* y = g_ln2 + (size_t)t * D;
    y[tid]       = d0 * inv * sc[tid]       + bi[tid];
    y[tid + 256] = d1 * inv * sc[tid + 256] + bi[tid + 256];
    y[tid + 512] = d2 * inv * sc[tid + 512] + bi[tid + 512];
}

// =========================================================================
extern "C" void kernel_launch(void* const* d_in, const int* in_sizes, int n_in,
                              void* d_out, int out_size)
{
    const float* x       = (const float*)d_in[0];
    const float* Wqkv    = (const float*)d_in[1];
    const float* q_scale = (const float*)d_in[2];
    const float* q_bias  = (const float*)d_in[3];
    const float* k_scale = (const float*)d_in[4];
    const float* k_bias  = (const float*)d_in[5];
    const float* o_scale = (const float*)d_in[6];
    const float* o_bias  = (const float*)d_in[7];
    const float* Wout    = (const float*)d_in[8];
    const float* bout    = (const float*)d_in[9];
    float* out = (float*)d_out;

    float *p_qkv = nullptr, *p_ln2 = nullptr;
    cudaGetSymbolAddress((void**)&p_qkv, g_qkv);
    cudaGetSymbolAddress((void**)&p_ln2, g_ln2);

    // 1) QKV projection: [4096,768] @ [768,2304]
    gemm128<<<dim3(QKVN / 128, TOK / 128), 256>>>(x, Wqkv, nullptr, p_qkv,
                                                  TOK, QKVN, D);
    // 2) per-head LN of q (scaled) and k
    ln_qk<<<(2 * B * H * P) / 8, 256>>>(q_scale, q_bias, k_scale, k_bias);
    // 3) flash attention
    cudaFuncSetAttribute(attn_kernel, cudaFuncAttributeMaxDynamicSharedMemorySize,
                         SMEM_ATTN);
    attn_kernel<<<dim3(B * H, P / 128), 256, SMEM_ATTN>>>();
    // 4) final LN over D
    ln_final<<<TOK, 256>>>(o_scale, o_bias);
    // 5) output projection with bias: [4096,768] @ [768,768] + b
    gemm128<<<dim3(D / 128, TOK / 128), 256>>>(p_ln2, Wout, bout, out,
                                               TOK, D, D);
}

// round 6
// speedup vs baseline: 1.4308x; 1.4308x over previous
#include <cuda_runtime.h>
#include <cuda_bf16.h>
#include <cstdint>
#include <math.h>

#define EPS 1e-6f
constexpr int B = 2, P = 2048, D = 768, H = 12, HD = 64;
constexpr int TOK = B * P;        // 4096
constexpr int QKVN = 3 * D;       // 2304

// ---------------- scratch (static device globals; no allocation) ----------------
__device__ float g_qkv[TOK * QKVN];       // qkv projection, token-major [tok][2304]
__device__ float g_qln[B * H * P * HD];   // layernormed q (* hd^-0.5), [bh][p][hd]
__device__ float g_kln[B * H * P * HD];   // layernormed k
__device__ float g_att[TOK * D];          // attention output, token-major

// split-bf16 operands for tensor-core GEMMs (all K-major)
__device__ __nv_bfloat16 g_xh[TOK * D];        // x hi
__device__ __nv_bfloat16 g_xl[TOK * D];        // x lo
__device__ __nv_bfloat16 g_wqh[QKVN * D];      // W_qkv^T hi  [2304][768]
__device__ __nv_bfloat16 g_wql[QKVN * D];
__device__ __nv_bfloat16 g_woh[D * D];         // W_out^T hi  [768][768]
__device__ __nv_bfloat16 g_wol[D * D];
__device__ __nv_bfloat16 g_a2h[TOK * D];       // ln_final output hi
__device__ __nv_bfloat16 g_a2l[TOK * D];

// ======================= base-target PTX helpers =======================
__device__ __forceinline__ uint32_t smem_u32(const void* p) {
    uint32_t a;
    asm("{ .reg .u64 t; cvta.to.shared.u64 t, %1; cvt.u32.u64 %0, t; }" : "=r"(a) : "l"(p));
    return a;
}
#define CP_ASYNC16(dst, src) \
    asm volatile("cp.async.cg.shared.global [%0], [%1], 16;" :: "r"(dst), "l"(src))
#define CP_COMMIT() asm volatile("cp.async.commit_group;" ::: "memory")
#define CP_WAIT0()  asm volatile("cp.async.wait_group 0;" ::: "memory")

__device__ __forceinline__ void ldsm_x4(uint32_t& r0, uint32_t& r1, uint32_t& r2,
                                        uint32_t& r3, uint32_t addr) {
    asm volatile("ldmatrix.sync.aligned.m8n8.x4.shared.b16 {%0,%1,%2,%3}, [%4];"
                 : "=r"(r0), "=r"(r1), "=r"(r2), "=r"(r3) : "r"(addr));
}
__device__ __forceinline__ void mma16816(float* c, const uint32_t* a, const uint32_t* b) {
    asm volatile(
        "mma.sync.aligned.m16n8k16.row.col.f32.bf16.bf16.f32 "
        "{%0,%1,%2,%3}, {%4,%5,%6,%7}, {%8,%9}, {%0,%1,%2,%3};"
        : "+f"(c[0]), "+f"(c[1]), "+f"(c[2]), "+f"(c[3])
        : "r"(a[0]), "r"(a[1]), "r"(a[2]), "r"(a[3]), "r"(b[0]), "r"(b[1]));
}

// =========================================================================
// Split fp32 -> bf16 hi/lo, same layout.
// =========================================================================
__global__ __launch_bounds__(256) void conv_split(
    const float* __restrict__ src, __nv_bfloat16* __restrict__ hi,
    __nv_bfloat16* __restrict__ lo, int n4)
{
    int i = blockIdx.x * blockDim.x + threadIdx.x;
    if (i >= n4) return;
    float4 v = ((const float4*)src)[i];
    __nv_bfloat16 h0 = __float2bfloat16(v.x), h1 = __float2bfloat16(v.y);
    __nv_bfloat16 h2 = __float2bfloat16(v.z), h3 = __float2bfloat16(v.w);
    __nv_bfloat162* hp = (__nv_bfloat162*)hi;
    __nv_bfloat162* lp = (__nv_bfloat162*)lo;
    hp[2 * i] = __nv_bfloat162(h0, h1);
    hp[2 * i + 1] = __nv_bfloat162(h2, h3);
    lp[2 * i] = __nv_bfloat162(__float2bfloat16(v.x - __bfloat162float(h0)),
                               __float2bfloat16(v.y - __bfloat162float(h1)));
    lp[2 * i + 1] = __nv_bfloat162(__float2bfloat16(v.z - __bfloat162float(h2)),
                                   __float2bfloat16(v.w - __bfloat162float(h3)));
}

// =========================================================================
// Transpose + split: W[K][N] f32 -> T[N][K] bf16 hi/lo.  32x32 tiles.
// =========================================================================
__global__ __launch_bounds__(256) void conv_wT(
    const float* __restrict__ W, __nv_bfloat16* __restrict__ Th,
    __nv_bfloat16* __restrict__ Tl, int K, int N)
{
    __shared__ float tile[32][33];
    int n0 = blockIdx.x * 32, k0 = blockIdx.y * 32;
    int tx = threadIdx.x, ty = threadIdx.y;
#pragma unroll
    for (int j = 0; j < 4; j++)
        tile[ty + 8 * j][tx] = W[(size_t)(k0 + ty + 8 * j) * N + n0 + tx];
    __syncthreads();
#pragma unroll
    for (int j = 0; j < 4; j++) {
        float v = tile[tx][ty + 8 * j];
        __nv_bfloat16 h = __float2bfloat16(v);
        size_t o = (size_t)(n0 + ty + 8 * j) * K + k0 + tx;
        Th[o] = h;
        Tl[o] = __float2bfloat16(v - __bfloat162float(h));
    }
}

// =========================================================================
// HMMA split-bf16 GEMM: C[M,N] = A[M,K] @ Bt[N,K]^T (+bias), fp32 accum.
// = Ah*Bh + Al*Bh + Ah*Bl.  128x128 CTA tile, 8 warps (2x4), 64x32 warptile,
// K-chunk 64, cp.async double-buffered SMEM, padded row stride 72 bf16.
// =========================================================================
constexpr int KC = 64;
constexpr int LDSW = 72;                         // bf16 elements per smem row
constexpr int TILE_BYTES = 128 * LDSW * 2;       // 18432
constexpr int GEMM_SMEM = 4 * TILE_BYTES;        // A/B x double buffer = 73728

__global__ __launch_bounds__(256) void gemm_mma(
    const __nv_bfloat16* __restrict__ Ah, const __nv_bfloat16* __restrict__ Al,
    const __nv_bfloat16* __restrict__ Bh, const __nv_bfloat16* __restrict__ Bl,
    const float* __restrict__ bias, float* __restrict__ C, int M, int N, int K)
{
    extern __shared__ char sm[];
    uint32_t sbase = smem_u32(sm);
    int tid = threadIdx.x, lane = tid & 31, wid = tid >> 5;
    int bm = blockIdx.y * 128, bn = blockIdx.x * 128;
    int m0 = (wid >> 2) * 64, n0 = (wid & 3) * 32;

    const int nkc = K / KC, nch = 3 * nkc;

    auto issue_load = [&](int c, int buf) {
        int term = c / nkc, kc = c - term * nkc;
        const __nv_bfloat16* Ag = ((term == 1) ? Al : Ah) + (size_t)bm * K + kc * KC;
        const __nv_bfloat16* Bg = ((term == 2) ? Bl : Bh) + (size_t)bn * K + kc * KC;
        uint32_t as = sbase + buf * 2 * TILE_BYTES;
        uint32_t bs = as + TILE_BYTES;
#pragma unroll
        for (int i = 0; i < 4; i++) {
            int u = tid + i * 256;           // 0..1023
            int row = u >> 3, v = u & 7;
            CP_ASYNC16(as + row * 144 + v * 16, Ag + (size_t)row * K + v * 8);
            CP_ASYNC16(bs + row * 144 + v * 16, Bg + (size_t)row * K + v * 8);
        }
        CP_COMMIT();
    };

    float acc[4][4][4];
#pragma unroll
    for (int mt = 0; mt < 4; mt++)
#pragma unroll
        for (int nt = 0; nt < 4; nt++)
#pragma unroll
            for (int j = 0; j < 4; j++) acc[mt][nt][j] = 0.f;

    issue_load(0, 0);
    for (int c = 0; c < nch; c++) {
        CP_WAIT0();
        __syncthreads();
        if (c + 1 < nch) issue_load(c + 1, (c + 1) & 1);

        uint32_t as = sbase + (c & 1) * 2 * TILE_BYTES;
        uint32_t bs = as + TILE_BYTES;
#pragma unroll
        for (int ks = 0; ks < 4; ks++) {
            int k0 = ks * 16;
            uint32_t a[4][4], b[4][2];
#pragma unroll
            for (int mt = 0; mt < 4; mt++) {
                uint32_t addr = as + (m0 + mt * 16 + (lane & 15)) * 144
                              + (k0 + (lane >> 4) * 8) * 2;
                ldsm_x4(a[mt][0], a[mt][1], a[mt][2], a[mt][3], addr);
            }
#pragma unroll
            for (int p = 0; p < 2; p++) {
                int nn = n0 + p * 16 + (lane >> 4) * 8 + (lane & 7);
                int kk = k0 + ((lane >> 3) & 1) * 8;
                uint32_t r0, r1, r2, r3;
                ldsm_x4(r0, r1, r2, r3, bs + nn * 144 + kk * 2);
                b[2 * p][0] = r0; b[2 * p][1] = r1;
                b[2 * p + 1][0] = r2; b[2 * p + 1][1] = r3;
            }
#pragma unroll
            for (int mt = 0; mt < 4; mt++)
#pragma unroll
                for (int nt = 0; nt < 4; nt++)
                    mma16816(acc[mt][nt], a[mt], b[nt]);
        }
        __syncthreads();
    }

    // epilogue
    int g = lane >> 2, t2 = (lane & 3) * 2;
#pragma unroll
    for (int mt = 0; mt < 4; mt++) {
        int row = bm + m0 + mt * 16 + g;
#pragma unroll
        for (int nt = 0; nt < 4; nt++) {
            int col = bn + n0 + nt * 8 + t2;
            float bx = 0.f, by = 0.f;
            if (bias) { bx = bias[col]; by = bias[col + 1]; }
            float2 lo = make_float2(acc[mt][nt][0] + bx, acc[mt][nt][1] + by);
            float2 hi = make_float2(acc[mt][nt][2] + bx, acc[mt][nt][3] + by);
            *(float2*)&C[(size_t)row * N + col] = lo;
            *(float2*)&C[(size_t)(row + 8) * N + col] = hi;
        }
    }
}

// =========================================================================
// Per-head LayerNorm over hd=64 for q and k.  One warp per (kind, b, h, p).
// =========================================================================
__global__ __launch_bounds__(256) void ln_qk(
    const float* __restrict__ qs, const float* __restrict__ qb,
    const float* __restrict__ ks, const float* __restrict__ kb)
{
    int gw = (blockIdx.x * blockDim.x + threadIdx.x) >> 5;
    int lane = threadIdx.x & 31;
    const int ROWS = B * H * P;
    int kind = gw / ROWS;
    int idx = gw - kind * ROWS;
    int b = idx / (H * P);
    int h = (idx / P) % H;
    int p = idx % P;

    const float* src = g_qkv + (size_t)(b * P + p) * QKVN + kind * D + h * HD;
    float x0 = src[lane], x1 = src[lane + 32];

    float s = x0 + x1;
#pragma unroll
    for (int o = 16; o; o >>= 1) s += __shfl_xor_sync(0xffffffffu, s, o);
    float mean = s * (1.0f / 64.0f);
    float d0 = x0 - mean, d1 = x1 - mean;
    float v = d0 * d0 + d1 * d1;
#pragma unroll
    for (int o = 16; o; o >>= 1) v += __shfl_xor_sync(0xffffffffu, v, o);
    float inv = rsqrtf(v * (1.0f / 64.0f) + EPS);

    const float* sc = kind ? ks : qs;
    const float* bi = kind ? kb : qb;
    float mul = kind ? 1.0f : 0.125f;
    float y0 = (d0 * inv * sc[lane] + bi[lane]) * mul;
    float y1 = (d1 * inv * sc[lane + 32] + bi[lane + 32]) * mul;

    float* dst = (kind ? g_kln : g_qln) + (size_t)((b * H + h) * P + p) * HD;
    dst[lane] = y0;
    dst[lane + 32] = y1;
}

// =========================================================================
// Flash attention (SIMT): grid (B*H, P/128), 256 threads.
// =========================================================================
constexpr int SMEM_ATTN = (64 * 132 + 64 * 68 + 64 * 68 + 128 * 68) * 4;

__global__ __launch_bounds__(256) void attn_kernel()
{
    extern __shared__ float smf[];
    float* Qs = smf;
    float* Ks = Qs + 64 * 132;
    float* Vs = Ks + 64 * 68;
    float* Ps = Vs + 64 * 68;

    int bh = blockIdx.x;
    int q0 = blockIdx.y * 128;
    int tid = threadIdx.x, tx = tid & 15, ty = tid >> 4;
    int b = bh / H, h = bh - b * H;

    const float* Qg = g_qln + (size_t)bh * P * HD + (size_t)q0 * HD;
    const float* Kg = g_kln + (size_t)bh * P * HD;
    const float* Vg = g_qkv + (size_t)b * P * QKVN + 2 * D + h * HD;

#pragma unroll
    for (int i = 0; i < 32; i++) {
        int l = tid + i * 256;
        Qs[(l & 63) * 132 + (l >> 6)] = Qg[l];
    }

    float m[8], lsum[8], O[8][4];
#pragma unroll
    for (int i = 0; i < 8; i++) {
        m[i] = -1e30f; lsum[i] = 0.f;
#pragma unroll
        for (int j = 0; j < 4; j++) O[i][j] = 0.f;
    }

    for (int kb = 0; kb < P; kb += 64) {
        __syncthreads();
#pragma unroll
        for (int i = 0; i < 16; i++) {
            int l = tid + i * 256;
            int key = l >> 6, d = l & 63;
            Ks[d * 68 + key] = Kg[(size_t)(kb + key) * HD + d];
            Vs[key * 68 + d] = Vg[(size_t)(kb + key) * QKVN + d];
        }
        __syncthreads();

        float S[8][4];
#pragma unroll
        for (int i = 0; i < 8; i++)
#pragma unroll
            for (int j = 0; j < 4; j++) S[i][j] = 0.f;

#pragma unroll 4
        for (int d = 0; d < 64; d++) {
            float4 a0 = *(const float4*)&Qs[d * 132 + ty * 8];
            float4 a1 = *(const float4*)&Qs[d * 132 + ty * 8 + 4];
            float4 bb = *(const float4*)&Ks[d * 68 + tx * 4];
            float a[8] = {a0.x, a0.y, a0.z, a0.w, a1.x, a1.y, a1.z, a1.w};
            float bv[4] = {bb.x, bb.y, bb.z, bb.w};
#pragma unroll
            for (int i = 0; i < 8; i++)
#pragma unroll
                for (int j = 0; j < 4; j++)
                    S[i][j] = fmaf(a[i], bv[j], S[i][j]);
        }

#pragma unroll
        for (int i = 0; i < 8; i++) {
            float mx = fmaxf(fmaxf(S[i][0], S[i][1]), fmaxf(S[i][2], S[i][3]));
#pragma unroll
            for (int o = 8; o; o >>= 1)
                mx = fmaxf(mx, __shfl_xor_sync(0xffffffffu, mx, o, 16));
            float mn = fmaxf(m[i], mx);
            float corr = __expf(m[i] - mn);
            float p0 = __expf(S[i][0] - mn);
            float p1 = __expf(S[i][1] - mn);
            float p2 = __expf(S[i][2] - mn);
            float p3 = __expf(S[i][3] - mn);
            float ls = p0 + p1 + p2 + p3;
#pragma unroll
            for (int o = 8; o; o >>= 1)
                ls += __shfl_xor_sync(0xffffffffu, ls, o, 16);
            lsum[i] = lsum[i] * corr + ls;
            m[i] = mn;
            O[i][0] *= corr; O[i][1] *= corr; O[i][2] *= corr; O[i][3] *= corr;
            *(float4*)&Ps[(ty * 8 + i) * 68 + tx * 4] = make_float4(p0, p1, p2, p3);
        }
        __syncthreads();

#pragma unroll 4
        for (int kk = 0; kk < 64; kk++) {
            float4 v4 = *(const float4*)&Vs[kk * 68 + tx * 4];
            float vv[4] = {v4.x, v4.y, v4.z, v4.w};
#pragma unroll
            for (int i = 0; i < 8; i++) {
                float a = Ps[(ty * 8 + i) * 68 + kk];
                O[i][0] = fmaf(a, vv[0], O[i][0]);
                O[i][1] = fmaf(a, vv[1], O[i][1]);
                O[i][2] = fmaf(a, vv[2], O[i][2]);
                O[i][3] = fmaf(a, vv[3], O[i][3]);
            }
        }
    }

#pragma unroll
    for (int i = 0; i < 8; i++) {
        float invl = 1.0f / lsum[i];
        int row = q0 + ty * 8 + i;
        float4 o4 = make_float4(O[i][0] * invl, O[i][1] * invl,
                                O[i][2] * invl, O[i][3] * invl);
        *(float4*)&g_att[(size_t)(b * P + row) * D + h * HD + tx * 4] = o4;
    }
}

// =========================================================================
// Final LayerNorm over D=768, emits split bf16 for the output GEMM.
// =========================================================================
__global__ __launch_bounds__(256) void ln_final(
    const float* __restrict__ sc, const float* __restrict__ bi)
{
    __shared__ float red[8];
    int t = blockIdx.x;
    int tid = threadIdx.x;
    const float* x = g_att + (size_t)t * D;

    float v0 = x[tid], v1 = x[tid + 256], v2 = x[tid + 512];
    float s = v0 + v1 + v2;
#pragma unroll
    for (int o = 16; o; o >>= 1) s += __shfl_xor_sync(0xffffffffu, s, o);
    if ((tid & 31) == 0) red[tid >> 5] = s;
    __syncthreads();
    float tot = 0.f;
#pragma unroll
    for (int w = 0; w < 8; w++) tot += red[w];
    float mean = tot * (1.0f / 768.0f);

    float d0 = v0 - mean, d1 = v1 - mean, d2 = v2 - mean;
    float vv = d0 * d0 + d1 * d1 + d2 * d2;
#pragma unroll
    for (int o = 16; o; o >>= 1) vv += __shfl_xor_sync(0xffffffffu, vv, o);
    __syncthreads();
    if ((tid & 31) == 0) red[tid >> 5] = vv;
    __syncthreads();
    float vt = 0.f;
#pragma unroll
    for (int w = 0; w < 8; w++) vt += red[w];
    float inv = rsqrtf(vt * (1.0f / 768.0f) + EPS);

#pragma unroll
    for (int j = 0; j < 3; j++) {
        int idx = tid + j * 256;
        float dj = (j == 0 ? d0 : (j == 1 ? d1 : d2));
        float y = dj * inv * sc[idx] + bi[idx];
        __nv_bfloat16 hh = __float2bfloat16(y);
        size_t o = (size_t)t * D + idx;
        g_a2h[o] = hh;
        g_a2l[o] = __float2bfloat16(y - __bfloat162float(hh));
    }
}

// =========================================================================
extern "C" void kernel_launch(void* const* d_in, const int* in_sizes, int n_in,
                              void* d_out, int out_size)
{
    const float* x       = (const float*)d_in[0];
    const float* Wqkv    = (const float*)d_in[1];
    const float* q_scale = (const float*)d_in[2];
    const float* q_bias  = (const float*)d_in[3];
    const float* k_scale = (const float*)d_in[4];
    const float* k_bias  = (const float*)d_in[5];
    const float* o_scale = (const float*)d_in[6];
    const float* o_bias  = (const float*)d_in[7];
    const float* Wout    = (const float*)d_in[8];
    const float* bout    = (const float*)d_in[9];
    float* out = (float*)d_out;

    float *p_qkv = nullptr;
    __nv_bfloat16 *p_xh, *p_xl, *p_wqh, *p_wql, *p_woh, *p_wol, *p_a2h, *p_a2l;
    cudaGetSymbolAddress((void**)&p_qkv, g_qkv);
    cudaGetSymbolAddress((void**)&p_xh, g_xh);
    cudaGetSymbolAddress((void**)&p_xl, g_xl);
    cudaGetSymbolAddress((void**)&p_wqh, g_wqh);
    cudaGetSymbolAddress((void**)&p_wql, g_wql);
    cudaGetSymbolAddress((void**)&p_woh, g_woh);
    cudaGetSymbolAddress((void**)&p_wol, g_wol);
    cudaGetSymbolAddress((void**)&p_a2h, g_a2h);
    cudaGetSymbolAddress((void**)&p_a2l, g_a2l);

    cudaFuncSetAttribute(gemm_mma, cudaFuncAttributeMaxDynamicSharedMemorySize, GEMM_SMEM);
    cudaFuncSetAttribute(attn_kernel, cudaFuncAttributeMaxDynamicSharedMemorySize, SMEM_ATTN);

    // 0) split inputs/weights into bf16 hi/lo
    conv_split<<<(TOK * D / 4 + 255) / 256, 256>>>(x, p_xh, p_xl, TOK * D / 4);
    conv_wT<<<dim3(QKVN / 32, D / 32), dim3(32, 8)>>>(Wqkv, p_wqh, p_wql, D, QKVN);
    conv_wT<<<dim3(D / 32, D / 32), dim3(32, 8)>>>(Wout, p_woh, p_wol, D, D);

    // 1) QKV projection (HMMA): [4096,768] @ [768,2304]
    gemm_mma<<<dim3(QKVN / 128, TOK / 128), 256, GEMM_SMEM>>>(
        p_xh, p_xl, p_wqh, p_wql, nullptr, p_qkv, TOK, QKVN, D);

    // 2) per-head LN of q (scaled) and k
    ln_qk<<<(2 * B * H * P) / 8, 256>>>(q_scale, q_bias, k_scale, k_bias);

    // 3) flash attention (SIMT)
    attn_kernel<<<dim3(B * H, P / 128), 256, SMEM_ATTN>>>();

    // 4) final LN over D (emits split bf16)
    ln_final<<<TOK, 256>>>(o_scale, o_bias);

    // 5) output projection (HMMA) with bias
    gemm_mma<<<dim3(D / 128, TOK / 128), 256, GEMM_SMEM>>>(
        p_a2h, p_a2l, p_woh, p_wol, bout, out, TOK, D, D);
}

// round 7
// speedup vs baseline: 2.8209x; 1.9715x over previous
#include <cuda_runtime.h>
#include <cuda_bf16.h>
#include <cstdint>
#include <math.h>

#define EPS 1e-6f
constexpr int B = 2, P = 2048, D = 768, H = 12, HD = 64;
constexpr int TOK = B * P;        // 4096
constexpr int QKVN = 3 * D;       // 2304

// ---------------- scratch (static device globals; no allocation) ----------------
__device__ float g_qkv[TOK * QKVN];       // qkv projection, token-major
__device__ float g_att[TOK * D];          // attention output, token-major

// split-bf16 operands
__device__ __nv_bfloat16 g_xh[TOK * D];
__device__ __nv_bfloat16 g_xl[TOK * D];
__device__ __nv_bfloat16 g_wqh[QKVN * D];
__device__ __nv_bfloat16 g_wql[QKVN * D];
__device__ __nv_bfloat16 g_woh[D * D];
__device__ __nv_bfloat16 g_wol[D * D];
__device__ __nv_bfloat16 g_a2h[TOK * D];
__device__ __nv_bfloat16 g_a2l[TOK * D];
// attention operands, [bh][p][hd] bf16 hi/lo
__device__ __nv_bfloat16 g_qh[B * H * P * HD];
__device__ __nv_bfloat16 g_ql[B * H * P * HD];
__device__ __nv_bfloat16 g_kh[B * H * P * HD];
__device__ __nv_bfloat16 g_kl[B * H * P * HD];
__device__ __nv_bfloat16 g_vh[B * H * P * HD];
__device__ __nv_bfloat16 g_vl[B * H * P * HD];

// ======================= base-target PTX helpers =======================
__device__ __forceinline__ uint32_t smem_u32(const void* p) {
    uint32_t a;
    asm("{ .reg .u64 t; cvta.to.shared.u64 t, %1; cvt.u32.u64 %0, t; }" : "=r"(a) : "l"(p));
    return a;
}
#define CP_ASYNC16(dst, src) \
    asm volatile("cp.async.cg.shared.global [%0], [%1], 16;" :: "r"(dst), "l"(src))
#define CP_COMMIT() asm volatile("cp.async.commit_group;" ::: "memory")
#define CP_WAIT0()  asm volatile("cp.async.wait_group 0;" ::: "memory")

__device__ __forceinline__ void ldsm_x4(uint32_t& r0, uint32_t& r1, uint32_t& r2,
                                        uint32_t& r3, uint32_t addr) {
    asm volatile("ldmatrix.sync.aligned.m8n8.x4.shared.b16 {%0,%1,%2,%3}, [%4];"
                 : "=r"(r0), "=r"(r1), "=r"(r2), "=r"(r3) : "r"(addr));
}
__device__ __forceinline__ void ldsm_x4_t(uint32_t& r0, uint32_t& r1, uint32_t& r2,
                                          uint32_t& r3, uint32_t addr) {
    asm volatile("ldmatrix.sync.aligned.m8n8.x4.trans.shared.b16 {%0,%1,%2,%3}, [%4];"
                 : "=r"(r0), "=r"(r1), "=r"(r2), "=r"(r3) : "r"(addr));
}
__device__ __forceinline__ void mma16816(float* c, const uint32_t* a, const uint32_t* b) {
    asm volatile(
        "mma.sync.aligned.m16n8k16.row.col.f32.bf16.bf16.f32 "
        "{%0,%1,%2,%3}, {%4,%5,%6,%7}, {%8,%9}, {%0,%1,%2,%3};"
        : "+f"(c[0]), "+f"(c[1]), "+f"(c[2]), "+f"(c[3])
        : "r"(a[0]), "r"(a[1]), "r"(a[2]), "r"(a[3]), "r"(b[0]), "r"(b[1]));
}
__device__ __forceinline__ uint32_t packbf(__nv_bfloat16 lo, __nv_bfloat16 hi) {
    __nv_bfloat162 t(lo, hi);
    return *(uint32_t*)&t;
}

// =========================================================================
// Split fp32 -> bf16 hi/lo, same layout.
// =========================================================================
__global__ __launch_bounds__(256) void conv_split(
    const float* __restrict__ src, __nv_bfloat16* __restrict__ hi,
    __nv_bfloat16* __restrict__ lo, int n4)
{
    int i = blockIdx.x * blockDim.x + threadIdx.x;
    if (i >= n4) return;
    float4 v = ((const float4*)src)[i];
    __nv_bfloat16 h0 = __float2bfloat16(v.x), h1 = __float2bfloat16(v.y);
    __nv_bfloat16 h2 = __float2bfloat16(v.z), h3 = __float2bfloat16(v.w);
    __nv_bfloat162* hp = (__nv_bfloat162*)hi;
    __nv_bfloat162* lp = (__nv_bfloat162*)lo;
    hp[2 * i] = __nv_bfloat162(h0, h1);
    hp[2 * i + 1] = __nv_bfloat162(h2, h3);
    lp[2 * i] = __nv_bfloat162(__float2bfloat16(v.x - __bfloat162float(h0)),
                               __float2bfloat16(v.y - __bfloat162float(h1)));
    lp[2 * i + 1] = __nv_bfloat162(__float2bfloat16(v.z - __bfloat162float(h2)),
                                   __float2bfloat16(v.w - __bfloat162float(h3)));
}

// =========================================================================
// Transpose + split: W[K][N] f32 -> T[N][K] bf16 hi/lo.  32x32 tiles.
// =========================================================================
__global__ __launch_bounds__(256) void conv_wT(
    const float* __restrict__ W, __nv_bfloat16* __restrict__ Th,
    __nv_bfloat16* __restrict__ Tl, int K, int N)
{
    __shared__ float tile[32][33];
    int n0 = blockIdx.x * 32, k0 = blockIdx.y * 32;
    int tx = threadIdx.x, ty = threadIdx.y;
#pragma unroll
    for (int j = 0; j < 4; j++)
        tile[ty + 8 * j][tx] = W[(size_t)(k0 + ty + 8 * j) * N + n0 + tx];
    __syncthreads();
#pragma unroll
    for (int j = 0; j < 4; j++) {
        float v = tile[tx][ty + 8 * j];
        __nv_bfloat16 h = __float2bfloat16(v);
        size_t o = (size_t)(n0 + ty + 8 * j) * K + k0 + tx;
        Th[o] = h;
        Tl[o] = __float2bfloat16(v - __bfloat162float(h));
    }
}

// =========================================================================
// HMMA split-bf16 GEMM (unchanged from R6).
// =========================================================================
constexpr int KC = 64;
constexpr int LDSW = 72;
constexpr int TILE_BYTES = 128 * LDSW * 2;       // 18432
constexpr int GEMM_SMEM = 4 * TILE_BYTES;

__global__ __launch_bounds__(256) void gemm_mma(
    const __nv_bfloat16* __restrict__ Ah, const __nv_bfloat16* __restrict__ Al,
    const __nv_bfloat16* __restrict__ Bh, const __nv_bfloat16* __restrict__ Bl,
    const float* __restrict__ bias, float* __restrict__ C, int M, int N, int K)
{
    extern __shared__ char sm[];
    uint32_t sbase = smem_u32(sm);
    int tid = threadIdx.x, lane = tid & 31, wid = tid >> 5;
    int bm = blockIdx.y * 128, bn = blockIdx.x * 128;
    int m0 = (wid >> 2) * 64, n0 = (wid & 3) * 32;

    const int nkc = K / KC, nch = 3 * nkc;

    auto issue_load = [&](int c, int buf) {
        int term = c / nkc, kc = c - term * nkc;
        const __nv_bfloat16* Ag = ((term == 1) ? Al : Ah) + (size_t)bm * K + kc * KC;
        const __nv_bfloat16* Bg = ((term == 2) ? Bl : Bh) + (size_t)bn * K + kc * KC;
        uint32_t as = sbase + buf * 2 * TILE_BYTES;
        uint32_t bs = as + TILE_BYTES;
#pragma unroll
        for (int i = 0; i < 4; i++) {
            int u = tid + i * 256;
            int row = u >> 3, v = u & 7;
            CP_ASYNC16(as + row * 144 + v * 16, Ag + (size_t)row * K + v * 8);
            CP_ASYNC16(bs + row * 144 + v * 16, Bg + (size_t)row * K + v * 8);
        }
        CP_COMMIT();
    };

    float acc[4][4][4];
#pragma unroll
    for (int mt = 0; mt < 4; mt++)
#pragma unroll
        for (int nt = 0; nt < 4; nt++)
#pragma unroll
            for (int j = 0; j < 4; j++) acc[mt][nt][j] = 0.f;

    issue_load(0, 0);
    for (int c = 0; c < nch; c++) {
        CP_WAIT0();
        __syncthreads();
        if (c + 1 < nch) issue_load(c + 1, (c + 1) & 1);

        uint32_t as = sbase + (c & 1) * 2 * TILE_BYTES;
        uint32_t bs = as + TILE_BYTES;
#pragma unroll
        for (int ks = 0; ks < 4; ks++) {
            int k0 = ks * 16;
            uint32_t a[4][4], b[4][2];
#pragma unroll
            for (int mt = 0; mt < 4; mt++) {
                uint32_t addr = as + (m0 + mt * 16 + (lane & 15)) * 144
                              + (k0 + (lane >> 4) * 8) * 2;
                ldsm_x4(a[mt][0], a[mt][1], a[mt][2], a[mt][3], addr);
            }
#pragma unroll
            for (int p = 0; p < 2; p++) {
                int nn = n0 + p * 16 + (lane >> 4) * 8 + (lane & 7);
                int kk = k0 + ((lane >> 3) & 1) * 8;
                uint32_t r0, r1, r2, r3;
                ldsm_x4(r0, r1, r2, r3, bs + nn * 144 + kk * 2);
                b[2 * p][0] = r0; b[2 * p][1] = r1;
                b[2 * p + 1][0] = r2; b[2 * p + 1][1] = r3;
            }
#pragma unroll
            for (int mt = 0; mt < 4; mt++)
#pragma unroll
                for (int nt = 0; nt < 4; nt++)
                    mma16816(acc[mt][nt], a[mt], b[nt]);
        }
        __syncthreads();
    }

    int g = lane >> 2, t2 = (lane & 3) * 2;
#pragma unroll
    for (int mt = 0; mt < 4; mt++) {
        int row = bm + m0 + mt * 16 + g;
#pragma unroll
        for (int nt = 0; nt < 4; nt++) {
            int col = bn + n0 + nt * 8 + t2;
            float bx = 0.f, by = 0.f;
            if (bias) { bx = bias[col]; by = bias[col + 1]; }
            float2 lo = make_float2(acc[mt][nt][0] + bx, acc[mt][nt][1] + by);
            float2 hi = make_float2(acc[mt][nt][2] + bx, acc[mt][nt][3] + by);
            *(float2*)&C[(size_t)row * N + col] = lo;
            *(float2*)&C[(size_t)(row + 8) * N + col] = hi;
        }
    }
}

// =========================================================================
// Per-head LayerNorm over hd=64 for q and k -> bf16 hi/lo outputs.
// =========================================================================
__global__ __launch_bounds__(256) void ln_qk(
    const float* __restrict__ qs, const float* __restrict__ qb,
    const float* __restrict__ ks, const float* __restrict__ kb)
{
    int gw = (blockIdx.x * blockDim.x + threadIdx.x) >> 5;
    int lane = threadIdx.x & 31;
    const int ROWS = B * H * P;
    int kind = gw / ROWS;
    int idx = gw - kind * ROWS;
    int b = idx / (H * P);
    int h = (idx / P) % H;
    int p = idx % P;

    const float* src = g_qkv + (size_t)(b * P + p) * QKVN + kind * D + h * HD;
    float x0 = src[lane], x1 = src[lane + 32];

    float s = x0 + x1;
#pragma unroll
    for (int o = 16; o; o >>= 1) s += __shfl_xor_sync(0xffffffffu, s, o);
    float mean = s * (1.0f / 64.0f);
    float d0 = x0 - mean, d1 = x1 - mean;
    float v = d0 * d0 + d1 * d1;
#pragma unroll
    for (int o = 16; o; o >>= 1) v += __shfl_xor_sync(0xffffffffu, v, o);
    float inv = rsqrtf(v * (1.0f / 64.0f) + EPS);

    const float* sc = kind ? ks : qs;
    const float* bi = kind ? kb : qb;
    float mul = kind ? 1.0f : 0.125f;
    float y0 = (d0 * inv * sc[lane] + bi[lane]) * mul;
    float y1 = (d1 * inv * sc[lane + 32] + bi[lane + 32]) * mul;

    size_t off = (size_t)((b * H + h) * P + p) * HD;
    __nv_bfloat16* dh = (kind ? g_kh : g_qh) + off;
    __nv_bfloat16* dl = (kind ? g_kl : g_ql) + off;
    __nv_bfloat16 h0 = __float2bfloat16(y0), h1 = __float2bfloat16(y1);
    dh[lane] = h0;
    dh[lane + 32] = h1;
    dl[lane] = __float2bfloat16(y0 - __bfloat162float(h0));
    dl[lane + 32] = __float2bfloat16(y1 - __bfloat162float(h1));
}

// =========================================================================
// Extract V from qkv, split to bf16 hi/lo, head-major layout.
// =========================================================================
__global__ __launch_bounds__(256) void conv_v()
{
    int tok = blockIdx.x;
    int tid = threadIdx.x;
    int b = tok >> 11, p = tok & 2047;
    const float* src = g_qkv + (size_t)tok * QKVN + 2 * D;
#pragma unroll
    for (int j = tid; j < D; j += 256) {
        float v = src[j];
        int h = j >> 6, d = j & 63;
        size_t o = ((size_t)(b * H + h) * P + p) * HD + d;
        __nv_bfloat16 hh = __float2bfloat16(v);
        g_vh[o] = hh;
        g_vl[o] = __float2bfloat16(v - __bfloat162float(hh));
    }
}

// =========================================================================
// Flash attention on HMMA with split-bf16 precision.
// grid (B*H, P/128), 256 threads = 8 warps; warp w owns q rows w*16..+15.
// Key block 64.  S = Qh Kh^T + Ql Kh^T + Qh Kl^T;  O += Ph Vh + Pl Vh + Ph Vl.
// =========================================================================
constexpr int ATT_SMEM = 73728;   // qh,ql(128x72) + kh,kl,vh,vl(64x72) bf16

__global__ __launch_bounds__(256) void attn_mma()
{
    extern __shared__ char sm[];
    uint32_t sb = smem_u32(sm);
    const uint32_t sqh = sb, sql = sb + 18432;
    const uint32_t skh = sb + 36864, skl = sb + 46080;
    const uint32_t svh = sb + 55296, svl = sb + 64512;

    int bh = blockIdx.x, q0 = blockIdx.y * 128;
    int b = bh / H, h = bh - b * H;
    int tid = threadIdx.x, lane = tid & 31, w = tid >> 5;

    // load Q tiles (128 rows x 64 bf16, hi+lo)
    size_t qbase = ((size_t)bh * P + q0) * HD;
#pragma unroll
    for (int i = 0; i < 4; i++) {
        int u = tid + i * 256;
        int row = u >> 3, c = u & 7;
        CP_ASYNC16(sqh + row * 144 + c * 16, g_qh + qbase + (size_t)row * HD + c * 8);
        CP_ASYNC16(sql + row * 144 + c * 16, g_ql + qbase + (size_t)row * HD + c * 8);
    }
    CP_COMMIT();

    float m0r = -1e30f, m1r = -1e30f, l0r = 0.f, l1r = 0.f;
    float O[8][4];
#pragma unroll
    for (int nt = 0; nt < 8; nt++)
#pragma unroll
        for (int j = 0; j < 4; j++) O[nt][j] = 0.f;

    const int m0 = w * 16;

    for (int kb = 0; kb < P / 64; kb++) {
        size_t kbase = ((size_t)bh * P + kb * 64) * HD;
#pragma unroll
        for (int i = 0; i < 2; i++) {
            int u = tid + i * 256;
            int row = u >> 3, c = u & 7;
            uint32_t so = row * 144 + c * 16;
            size_t go = (size_t)row * HD + c * 8;
            CP_ASYNC16(skh + so, g_kh + kbase + go);
            CP_ASYNC16(skl + so, g_kl + kbase + go);
            CP_ASYNC16(svh + so, g_vh + kbase + go);
            CP_ASYNC16(svl + so, g_vl + kbase + go);
        }
        CP_COMMIT();
        CP_WAIT0();
        __syncthreads();

        // ---- S = Q K^T (3-term split) : sa[8 key-tiles][4] ----
        float sa[8][4];
#pragma unroll
        for (int nt = 0; nt < 8; nt++)
#pragma unroll
            for (int j = 0; j < 4; j++) sa[nt][j] = 0.f;

#pragma unroll
        for (int ks = 0; ks < 4; ks++) {
            int k0 = ks * 16;
            uint32_t qoff = (m0 + (lane & 15)) * 144 + (k0 + (lane >> 4) * 8) * 2;
            uint32_t aH[4], aL[4];
            ldsm_x4(aH[0], aH[1], aH[2], aH[3], sqh + qoff);
            ldsm_x4(aL[0], aL[1], aL[2], aL[3], sql + qoff);
#pragma unroll
            for (int j = 0; j < 4; j++) {
                int n0 = j * 16;
                uint32_t koff = (n0 + (lane >> 4) * 8 + (lane & 7)) * 144
                              + (k0 + ((lane >> 3) & 1) * 8) * 2;
                uint32_t bH[4], bL[4];
                ldsm_x4(bH[0], bH[1], bH[2], bH[3], skh + koff);
                ldsm_x4(bL[0], bL[1], bL[2], bL[3], skl + koff);
                mma16816(sa[2 * j],     aH, &bH[0]);
                mma16816(sa[2 * j + 1], aH, &bH[2]);
                mma16816(sa[2 * j],     aL, &bH[0]);
                mma16816(sa[2 * j + 1], aL, &bH[2]);
                mma16816(sa[2 * j],     aH, &bL[0]);
                mma16816(sa[2 * j + 1], aH, &bL[2]);
            }
        }

        // ---- online softmax (rows: r0 = m0+(lane>>2), r1 = r0+8) ----
        float mx0 = -1e30f, mx1 = -1e30f;
#pragma unroll
        for (int nt = 0; nt < 8; nt++) {
            mx0 = fmaxf(mx0, fmaxf(sa[nt][0], sa[nt][1]));
            mx1 = fmaxf(mx1, fmaxf(sa[nt][2], sa[nt][3]));
        }
        mx0 = fmaxf(mx0, __shfl_xor_sync(0xffffffffu, mx0, 1));
        mx0 = fmaxf(mx0, __shfl_xor_sync(0xffffffffu, mx0, 2));
        mx1 = fmaxf(mx1, __shfl_xor_sync(0xffffffffu, mx1, 1));
        mx1 = fmaxf(mx1, __shfl_xor_sync(0xffffffffu, mx1, 2));
        float mn0 = fmaxf(m0r, mx0), mn1 = fmaxf(m1r, mx1);
        float c0 = __expf(m0r - mn0), c1 = __expf(m1r - mn1);
        m0r = mn0; m1r = mn1;

        float s0 = 0.f, s1 = 0.f;
        uint32_t ph0[8], ph1[8], pl0[8], pl1[8];
#pragma unroll
        for (int nt = 0; nt < 8; nt++) {
            float p00 = __expf(sa[nt][0] - mn0);
            float p01 = __expf(sa[nt][1] - mn0);
            float p10 = __expf(sa[nt][2] - mn1);
            float p11 = __expf(sa[nt][3] - mn1);
            s0 += p00 + p01;
            s1 += p10 + p11;
            __nv_bfloat16 h00 = __float2bfloat16(p00), h01 = __float2bfloat16(p01);
            __nv_bfloat16 h10 = __float2bfloat16(p10), h11 = __float2bfloat16(p11);
            ph0[nt] = packbf(h00, h01);
            ph1[nt] = packbf(h10, h11);
            pl0[nt] = packbf(__float2bfloat16(p00 - __bfloat162float(h00)),
                             __float2bfloat16(p01 - __bfloat162float(h01)));
            pl1[nt] = packbf(__float2bfloat16(p10 - __bfloat162float(h10)),
                             __float2bfloat16(p11 - __bfloat162float(h11)));
        }
        s0 += __shfl_xor_sync(0xffffffffu, s0, 1);
        s0 += __shfl_xor_sync(0xffffffffu, s0, 2);
        s1 += __shfl_xor_sync(0xffffffffu, s1, 1);
        s1 += __shfl_xor_sync(0xffffffffu, s1, 2);
        l0r = l0r * c0 + s0;
        l1r = l1r * c1 + s1;
#pragma unroll
        for (int nt = 0; nt < 8; nt++) {
            O[nt][0] *= c0; O[nt][1] *= c0;
            O[nt][2] *= c1; O[nt][3] *= c1;
        }

        // ---- O += P V (3-term split); V frags via trans ldmatrix ----
#pragma unroll
        for (int ks = 0; ks < 4; ks++) {
            int k0 = ks * 16;
            uint32_t aPh[4] = {ph0[2 * ks], ph1[2 * ks], ph0[2 * ks + 1], ph1[2 * ks + 1]};
            uint32_t aPl[4] = {pl0[2 * ks], pl1[2 * ks], pl0[2 * ks + 1], pl1[2 * ks + 1]};
#pragma unroll
            for (int jn = 0; jn < 4; jn++) {
                int n0 = jn * 16;
                uint32_t voff = (k0 + ((lane >> 3) & 1) * 8 + (lane & 7)) * 144
                              + (n0 + (lane >> 4) * 8) * 2;
                uint32_t vH[4], vL[4];
                ldsm_x4_t(vH[0], vH[1], vH[2], vH[3], svh + voff);
                ldsm_x4_t(vL[0], vL[1], vL[2], vL[3], svl + voff);
                mma16816(O[2 * jn],     aPh, &vH[0]);
                mma16816(O[2 * jn + 1], aPh, &vH[2]);
                mma16816(O[2 * jn],     aPl, &vH[0]);
                mma16816(O[2 * jn + 1], aPl, &vH[2]);
                mma16816(O[2 * jn],     aPh, &vL[0]);
                mma16816(O[2 * jn + 1], aPh, &vL[2]);
            }
        }
        __syncthreads();
    }

    // ---- epilogue ----
    float inv0 = 1.0f / l0r, inv1 = 1.0f / l1r;
    int r0 = q0 + m0 + (lane >> 2), r1 = r0 + 8;
#pragma unroll
    for (int nt = 0; nt < 8; nt++) {
        int col = h * HD + nt * 8 + (lane & 3) * 2;
        *(float2*)&g_att[(size_t)(b * P + r0) * D + col] =
            make_float2(O[nt][0] * inv0, O[nt][1] * inv0);
        *(float2*)&g_att[(size_t)(b * P + r1) * D + col] =
            make_float2(O[nt][2] * inv1, O[nt][3] * inv1);
    }
}

// =========================================================================
// Final LayerNorm over D=768, emits split bf16 for the output GEMM.
// =========================================================================
__global__ __launch_bounds__(256) void ln_final(
    const float* __restrict__ sc, const float* __restrict__ bi)
{
    __shared__ float red[8];
    int t = blockIdx.x;
    int tid = threadIdx.x;
    const float* x = g_att + (size_t)t * D;

    float v0 = x[tid], v1 = x[tid + 256], v2 = x[tid + 512];
    float s = v0 + v1 + v2;
#pragma unroll
    for (int o = 16; o; o >>= 1) s += __shfl_xor_sync(0xffffffffu, s, o);
    if ((tid & 31) == 0) red[tid >> 5] = s;
    __syncthreads();
    float tot = 0.f;
#pragma unroll
    for (int w = 0; w < 8; w++) tot += red[w];
    float mean = tot * (1.0f / 768.0f);

    float d0 = v0 - mean, d1 = v1 - mean, d2 = v2 - mean;
    float vv = d0 * d0 + d1 * d1 + d2 * d2;
#pragma unroll
    for (int o = 16; o; o >>= 1) vv += __shfl_xor_sync(0xffffffffu, vv, o);
    __syncthreads();
    if ((tid & 31) == 0) red[tid >> 5] = vv;
    __syncthreads();
    float vt = 0.f;
#pragma unroll
    for (int w = 0; w < 8; w++) vt += red[w];
    float inv = rsqrtf(vt * (1.0f / 768.0f) + EPS);

#pragma unroll
    for (int j = 0; j < 3; j++) {
        int idx = tid + j * 256;
        float dj = (j == 0 ? d0 : (j == 1 ? d1 : d2));
        float y = dj * inv * sc[idx] + bi[idx];
        __nv_bfloat16 hh = __float2bfloat16(y);
        size_t o = (size_t)t * D + idx;
        g_a2h[o] = hh;
        g_a2l[o] = __float2bfloat16(y - __bfloat162float(hh));
    }
}

// =========================================================================
extern "C" void kernel_launch(void* const* d_in, const int* in_sizes, int n_in,
                              void* d_out, int out_size)
{
    const float* x       = (const float*)d_in[0];
    const float* Wqkv    = (const float*)d_in[1];
    const float* q_scale = (const float*)d_in[2];
    const float* q_bias  = (const float*)d_in[3];
    const float* k_scale = (const float*)d_in[4];
    const float* k_bias  = (const float*)d_in[5];
    const float* o_scale = (const float*)d_in[6];
    const float* o_bias  = (const float*)d_in[7];
    const float* Wout    = (const float*)d_in[8];
    const float* bout    = (const float*)d_in[9];
    float* out = (float*)d_out;

    float *p_qkv = nullptr;
    __nv_bfloat16 *p_xh, *p_xl, *p_wqh, *p_wql, *p_woh, *p_wol, *p_a2h, *p_a2l;
    cudaGetSymbolAddress((void**)&p_qkv, g_qkv);
    cudaGetSymbolAddress((void**)&p_xh, g_xh);
    cudaGetSymbolAddress((void**)&p_xl, g_xl);
    cudaGetSymbolAddress((void**)&p_wqh, g_wqh);
    cudaGetSymbolAddress((void**)&p_wql, g_wql);
    cudaGetSymbolAddress((void**)&p_woh, g_woh);
    cudaGetSymbolAddress((void**)&p_wol, g_wol);
    cudaGetSymbolAddress((void**)&p_a2h, g_a2h);
    cudaGetSymbolAddress((void**)&p_a2l, g_a2l);

    cudaFuncSetAttribute(gemm_mma, cudaFuncAttributeMaxDynamicSharedMemorySize, GEMM_SMEM);
    cudaFuncSetAttribute(attn_mma, cudaFuncAttributeMaxDynamicSharedMemorySize, ATT_SMEM);

    // 0) split inputs/weights into bf16 hi/lo
    conv_split<<<(TOK * D / 4 + 255) / 256, 256>>>(x, p_xh, p_xl, TOK * D / 4);
    conv_wT<<<dim3(QKVN / 32, D / 32), dim3(32, 8)>>>(Wqkv, p_wqh, p_wql, D, QKVN);
    conv_wT<<<dim3(D / 32, D / 32), dim3(32, 8)>>>(Wout, p_woh, p_wol, D, D);

    // 1) QKV projection (HMMA)
    gemm_mma<<<dim3(QKVN / 128, TOK / 128), 256, GEMM_SMEM>>>(
        p_xh, p_xl, p_wqh, p_wql, nullptr, p_qkv, TOK, QKVN, D);

    // 2) per-head LN of q/k -> bf16 hi/lo ; V extract/split
    ln_qk<<<(2 * B * H * P) / 8, 256>>>(q_scale, q_bias, k_scale, k_bias);
    conv_v<<<TOK, 256>>>();

    // 3) flash attention (HMMA, split precision)
    attn_mma<<<dim3(B * H, P / 128), 256, ATT_SMEM>>>();

    // 4) final LN over D (emits split bf16)
    ln_final<<<TOK, 256>>>(o_scale, o_bias);

    // 5) output projection (HMMA) with bias
    gemm_mma<<<dim3(D / 128, TOK / 128), 256, GEMM_SMEM>>>(
        p_a2h, p_a2l, p_woh, p_wol, bout, out, TOK, D, D);
}